// round 1
// baseline (speedup 1.0000x reference)
#include <cuda_runtime.h>
#include <math.h>

// ---------------------------------------------------------------------------
// Transformer-XL (MemTransformerLM) forward, fp32 baseline.
// Inputs (metadata order):
//  0 data i32[512,8]  1 target i32[512,8]  2 memory f32[6,512,8,1024]
//  3 emb_W f32[32000,1024] 4 r_w_bias[16,64] 5 r_r_bias[16,64]
//  6 Wq[6,1024,1024] 7 Wkv[6,1024,2048] 8 Wr[6,1024,1024] 9 Wo[6,1024,1024]
// 10 W1[6,1024,4096] 11 b1[6,4096] 12 W2[6,4096,1024] 13 b2[6,1024]
// 14 ln1_g 15 ln1_b 16 ln2_g 17 ln2_b  (each [6,1024])
// Output f32: loss[4096] ++ new_mems[6*512*8*1024]
// ---------------------------------------------------------------------------

#define QLENC   512
#define KLENC   1024
#define BSZC    8
#define NHEADC  16
#define DHEADC  64
#define DMODELC 1024
#define DINNERC 4096
#define NTOKC   32000
#define NLAYERC 6
#define NT      4096        // qlen*bsz tokens
#define KT      8192        // klen*bsz tokens

// ------------------------- scratch (device globals) ------------------------
__device__ float g_core[NT * DMODELC];
__device__ float g_xmem[KT * DMODELC];
__device__ float g_q [NT * DMODELC];
__device__ float g_qw[NT * DMODELC];
__device__ float g_qr[NT * DMODELC];
__device__ float g_kv[KT * 2 * DMODELC];
__device__ float g_rk [KLENC * DMODELC];
__device__ float g_pos[KLENC * DMODELC];
__device__ float g_scores[67108864];   // [b*16+n][512][1024]
__device__ float g_bd    [67108864];   // [n][4096][1024]
__device__ float g_vec[NT * DMODELC];
__device__ float g_tmp[NT * DMODELC];
__device__ float g_h1 [NT * DINNERC];
__device__ float g_logits[131072000];  // [4096][32000]

// ------------------------------- reductions --------------------------------
__device__ __forceinline__ float block_reduce_max(float v) {
    __shared__ float sd[256];
    int tid = threadIdx.x;
    sd[tid] = v;
    __syncthreads();
    #pragma unroll
    for (int s = 128; s > 0; s >>= 1) {
        if (tid < s) sd[tid] = fmaxf(sd[tid], sd[tid + s]);
        __syncthreads();
    }
    float r = sd[0];
    __syncthreads();
    return r;
}

__device__ __forceinline__ float block_reduce_sum(float v) {
    __shared__ float sd[256];
    int tid = threadIdx.x;
    sd[tid] = v;
    __syncthreads();
    #pragma unroll
    for (int s = 128; s > 0; s >>= 1) {
        if (tid < s) sd[tid] += sd[tid + s];
        __syncthreads();
    }
    float r = sd[0];
    __syncthreads();
    return r;
}

// --------------------------------- GEMM ------------------------------------
// C[M,N] = A[M,K] * op(B).  TB: B stored [N,K] row-major (B^T).
// EPI: 0 none, 1 +bias, 2 +bias,relu.  Batched via z with two-level strides:
// z1 = z/batch2, z2 = z%batch2; ptr += z1*s1 + z2*s2.
template<bool TB, int EPI>
__global__ void __launch_bounds__(256) gemm_k(
    const float* __restrict__ A, const float* __restrict__ B,
    float* __restrict__ C, const float* __restrict__ bias,
    int M, int N, int K, int lda, int ldb, int ldc,
    int batch2,
    long long sA1, long long sA2, long long sB1, long long sB2,
    long long sC1, long long sC2)
{
    int z = blockIdx.z;
    int z1 = z / batch2, z2 = z - z1 * batch2;
    A += z1 * sA1 + z2 * sA2;
    B += z1 * sB1 + z2 * sB2;
    C += z1 * sC1 + z2 * sC2;

    __shared__ float As[16][68];
    __shared__ float Bs[16][68];

    const int tid = threadIdx.x;
    const int tx = tid & 15, ty = tid >> 4;
    const int m0 = blockIdx.y * 64, n0 = blockIdx.x * 64;
    const int loadRow = tid >> 4, loadCol = tid & 15;
    const int bRow = tid >> 6, bCol = tid & 63;

    float acc[4][4];
    #pragma unroll
    for (int i = 0; i < 4; i++)
        #pragma unroll
        for (int j = 0; j < 4; j++) acc[i][j] = 0.f;

    for (int k0 = 0; k0 < K; k0 += 16) {
        #pragma unroll
        for (int r = 0; r < 4; r++) {
            int m = loadRow + r * 16;
            As[loadCol][m] = A[(long long)(m0 + m) * lda + (k0 + loadCol)];
        }
        if (TB) {
            #pragma unroll
            for (int r = 0; r < 4; r++) {
                int n = loadRow + r * 16;
                Bs[loadCol][n] = B[(long long)(n0 + n) * ldb + (k0 + loadCol)];
            }
        } else {
            #pragma unroll
            for (int r = 0; r < 4; r++) {
                int kk = bRow + r * 4;
                Bs[kk][bCol] = B[(long long)(k0 + kk) * ldb + (n0 + bCol)];
            }
        }
        __syncthreads();
        #pragma unroll
        for (int kk = 0; kk < 16; kk++) {
            float4 a4 = *(const float4*)&As[kk][ty * 4];
            float4 b4 = *(const float4*)&Bs[kk][tx * 4];
            float av[4] = {a4.x, a4.y, a4.z, a4.w};
            float bv[4] = {b4.x, b4.y, b4.z, b4.w};
            #pragma unroll
            for (int i = 0; i < 4; i++)
                #pragma unroll
                for (int j = 0; j < 4; j++)
                    acc[i][j] = fmaf(av[i], bv[j], acc[i][j]);
        }
        __syncthreads();
    }

    #pragma unroll
    for (int i = 0; i < 4; i++) {
        int row = m0 + ty * 4 + i;
        #pragma unroll
        for (int j = 0; j < 4; j++) {
            int col = n0 + tx * 4 + j;
            float c = acc[i][j];
            if (EPI >= 1) c += bias[col];
            if (EPI == 2) c = fmaxf(c, 0.f);
            C[(long long)row * ldc + col] = c;
        }
    }
}

// ------------------------------ small kernels ------------------------------
__global__ void embed_k(const int* __restrict__ data, const float* __restrict__ emb,
                        float* __restrict__ core, float* __restrict__ memout)
{
    int t = blockIdx.x;
    int tok = data[t];
    const float* src = emb + (long long)tok * DMODELC;
    float* c  = core   + (long long)t * DMODELC;
    float* mo = memout + (long long)t * DMODELC;
    #pragma unroll
    for (int r = 0; r < 4; r++) {
        int d = threadIdx.x + 256 * r;
        float v = src[d];
        c[d] = v;
        mo[d] = v;
    }
}

__global__ void pos_k(float* __restrict__ pos)
{
    int k = blockIdx.x;
    float p = (float)(KLENC - 1 - k);
    #pragma unroll
    for (int r = 0; r < 4; r++) {
        int c = threadIdx.x + 256 * r;
        int j = (c < 512) ? c : (c - 512);
        float invf = 1.0f / powf(10000.0f, (2.0f * (float)j) / 1024.0f);
        float ang = p * invf;
        pos[(long long)k * DMODELC + c] = (c < 512) ? sinf(ang) : cosf(ang);
    }
}

__global__ void qwqr_k(const float* __restrict__ q, const float* __restrict__ rwb,
                       const float* __restrict__ rrb,
                       float* __restrict__ qw, float* __restrict__ qr)
{
    long long idx = (long long)blockIdx.x * 256 + threadIdx.x;
    int c = (int)(idx & 1023);           // c = n*64 + d, rwb/rrb flat [1024]
    float v = q[idx];
    qw[idx] = v + rwb[c];
    qr[idx] = v + rrb[c];
}

// score = (AC[i,j] + BD_raw[i, j+511-i]) * 0.125 for j <= i+512 else -1e30;
// softmax over j; write probs in place of AC.
__global__ void softmax_k(float* __restrict__ scores, const float* __restrict__ bd)
{
    int i  = blockIdx.x;           // 0..511
    int bn = blockIdx.y;           // 0..127
    int b = bn >> 4, n = bn & 15;
    float* ac = scores + (long long)bn * (QLENC * KLENC) + (long long)i * KLENC;
    const float* bdr = bd + (long long)n * ((long long)NT * KLENC)
                          + (long long)(i * BSZC + b) * KLENC;
    int shift = QLENC - 1 - i;     // 511 - i
    int lim = i + 512;             // last unmasked j

    float vals[4];
    float lmax = -1e30f;
    #pragma unroll
    for (int r = 0; r < 4; r++) {
        int j = threadIdx.x + 256 * r;
        float v = -1e30f;
        if (j <= lim) v = (ac[j] + bdr[j + shift]) * 0.125f;
        vals[r] = v;
        lmax = fmaxf(lmax, v);
    }
    float rmax = block_reduce_max(lmax);
    float lsum = 0.f;
    #pragma unroll
    for (int r = 0; r < 4; r++) {
        float e = expf(vals[r] - rmax);   // masked -> exp(-1e30) = 0
        vals[r] = e;
        lsum += e;
    }
    float rsum = block_reduce_sum(lsum);
    float inv = 1.0f / rsum;
    #pragma unroll
    for (int r = 0; r < 4; r++) {
        int j = threadIdx.x + 256 * r;
        ac[j] = vals[r] * inv;
    }
}

// dst = LayerNorm(x + res); optionally also copy to dst2 (mems output)
__global__ void ln_k(const float* __restrict__ x, const float* __restrict__ res,
                     const float* __restrict__ g, const float* __restrict__ bb,
                     float* __restrict__ dst, float* __restrict__ dst2)
{
    long long t = blockIdx.x;
    const float* xr = x   + t * DMODELC;
    const float* rr = res + t * DMODELC;
    float v[4];
    float s = 0.f, sq = 0.f;
    #pragma unroll
    for (int r = 0; r < 4; r++) {
        int d = threadIdx.x + 256 * r;
        float u = xr[d] + rr[d];
        v[r] = u;
        s += u;
        sq += u * u;
    }
    float sum  = block_reduce_sum(s);
    float sums = block_reduce_sum(sq);
    float mean = sum * (1.0f / 1024.0f);
    float var  = sums * (1.0f / 1024.0f) - mean * mean;
    float rstd = rsqrtf(var + 1e-5f);
    #pragma unroll
    for (int r = 0; r < 4; r++) {
        int d = threadIdx.x + 256 * r;
        float y = (v[r] - mean) * rstd * g[d] + bb[d];
        dst[t * DMODELC + d] = y;
        if (dst2) dst2[t * DMODELC + d] = y;
    }
}

__global__ void loss_k(const float* __restrict__ logits, const int* __restrict__ target,
                       float* __restrict__ out)
{
    int t = blockIdx.x;
    const float* lr = logits + (long long)t * NTOKC;
    float lmax = -1e30f;
    for (int j = threadIdx.x; j < NTOKC; j += 256) lmax = fmaxf(lmax, lr[j]);
    float m = block_reduce_max(lmax);
    float lsum = 0.f;
    for (int j = threadIdx.x; j < NTOKC; j += 256) lsum += expf(lr[j] - m);
    float s = block_reduce_sum(lsum);
    if (threadIdx.x == 0) {
        int tg = target[t];
        out[t] = -(lr[tg] - m - logf(s));
    }
}

// ------------------------------ host dispatch ------------------------------
static inline void launch_gemm(bool tb, int epi,
    const float* A, const float* B, float* C, const float* bias,
    int M, int N, int K, int lda, int ldb, int ldc,
    int batch = 1, int batch2 = 1,
    long long sA1 = 0, long long sA2 = 0,
    long long sB1 = 0, long long sB2 = 0,
    long long sC1 = 0, long long sC2 = 0)
{
    dim3 grid(N / 64, M / 64, batch), block(256);
    if (tb)
        gemm_k<true, 0><<<grid, block>>>(A, B, C, bias, M, N, K, lda, ldb, ldc,
                                         batch2, sA1, sA2, sB1, sB2, sC1, sC2);
    else if (epi == 0)
        gemm_k<false, 0><<<grid, block>>>(A, B, C, bias, M, N, K, lda, ldb, ldc,
                                          batch2, sA1, sA2, sB1, sB2, sC1, sC2);
    else if (epi == 1)
        gemm_k<false, 1><<<grid, block>>>(A, B, C, bias, M, N, K, lda, ldb, ldc,
                                          batch2, sA1, sA2, sB1, sB2, sC1, sC2);
    else
        gemm_k<false, 2><<<grid, block>>>(A, B, C, bias, M, N, K, lda, ldb, ldc,
                                          batch2, sA1, sA2, sB1, sB2, sC1, sC2);
}

extern "C" void kernel_launch(void* const* d_in, const int* in_sizes, int n_in,
                              void* d_out, int out_size)
{
    const int*   data   = (const int*)  d_in[0];
    const int*   target = (const int*)  d_in[1];
    const float* memory = (const float*)d_in[2];
    const float* emb_W  = (const float*)d_in[3];
    const float* rwb    = (const float*)d_in[4];
    const float* rrb    = (const float*)d_in[5];
    const float* Wq     = (const float*)d_in[6];
    const float* Wkv    = (const float*)d_in[7];
    const float* Wr     = (const float*)d_in[8];
    const float* Wo     = (const float*)d_in[9];
    const float* W1     = (const float*)d_in[10];
    const float* b1     = (const float*)d_in[11];
    const float* W2     = (const float*)d_in[12];
    const float* b2     = (const float*)d_in[13];
    const float* ln1g   = (const float*)d_in[14];
    const float* ln1b   = (const float*)d_in[15];
    const float* ln2g   = (const float*)d_in[16];
    const float* ln2b   = (const float*)d_in[17];
    float* out = (float*)d_out;

    float *core, *xmem, *q, *qw, *qr, *kv, *rk, *pos, *scores, *bd, *vec, *tmp, *h1, *logits;
    cudaGetSymbolAddress((void**)&core,   g_core);
    cudaGetSymbolAddress((void**)&xmem,   g_xmem);
    cudaGetSymbolAddress((void**)&q,      g_q);
    cudaGetSymbolAddress((void**)&qw,     g_qw);
    cudaGetSymbolAddress((void**)&qr,     g_qr);
    cudaGetSymbolAddress((void**)&kv,     g_kv);
    cudaGetSymbolAddress((void**)&rk,     g_rk);
    cudaGetSymbolAddress((void**)&pos,    g_pos);
    cudaGetSymbolAddress((void**)&scores, g_scores);
    cudaGetSymbolAddress((void**)&bd,     g_bd);
    cudaGetSymbolAddress((void**)&vec,    g_vec);
    cudaGetSymbolAddress((void**)&tmp,    g_tmp);
    cudaGetSymbolAddress((void**)&h1,     g_h1);
    cudaGetSymbolAddress((void**)&logits, g_logits);

    const long long LSLOT = (long long)NT * DMODELC;   // 4194304 floats / mem slot
    float* mems_out = out + NT;                        // after loss[4096]

    // word embedding -> core, and new_mems slot 0
    embed_k<<<NT, 256>>>(data, emb_W, core, mems_out);
    // relative position embedding
    pos_k<<<KLENC, 256>>>(pos);

    for (int l = 0; l < NLAYERC; l++) {
        const float* Wq_l  = Wq  + (long long)l * DMODELC * DMODELC;
        const float* Wkv_l = Wkv + (long long)l * DMODELC * 2 * DMODELC;
        const float* Wr_l  = Wr  + (long long)l * DMODELC * DMODELC;
        const float* Wo_l  = Wo  + (long long)l * DMODELC * DMODELC;
        const float* W1_l  = W1  + (long long)l * DMODELC * DINNERC;
        const float* b1_l  = b1  + (long long)l * DINNERC;
        const float* W2_l  = W2  + (long long)l * DINNERC * DMODELC;
        const float* b2_l  = b2  + (long long)l * DMODELC;

        // x_mem = [memory[l]; core]
        cudaMemcpyAsync(xmem, memory + (long long)l * LSLOT, LSLOT * sizeof(float),
                        cudaMemcpyDeviceToDevice, 0);
        cudaMemcpyAsync(xmem + LSLOT, core, LSLOT * sizeof(float),
                        cudaMemcpyDeviceToDevice, 0);

        // q = core @ Wq[l]
        launch_gemm(false, 0, core, Wq_l, q, nullptr, NT, DMODELC, DMODELC,
                    DMODELC, DMODELC, DMODELC);
        // qw = q + r_w_bias, qr = q + r_r_bias
        qwqr_k<<<(NT * DMODELC) / 256, 256>>>(q, rwb, rrb, qw, qr);
        // kv = x_mem @ Wkv[l]
        launch_gemm(false, 0, xmem, Wkv_l, kv, nullptr, KT, 2 * DMODELC, DMODELC,
                    DMODELC, 2 * DMODELC, 2 * DMODELC);
        // r_k = pos @ Wr[l]
        launch_gemm(false, 0, pos, Wr_l, rk, nullptr, KLENC, DMODELC, DMODELC,
                    DMODELC, DMODELC, DMODELC);

        // AC[b,n]: [512,64] x k[b,n]^T[64,1024] -> scores[bn]
        launch_gemm(true, 0,
                    qw, kv, scores, nullptr,
                    QLENC, KLENC, DHEADC,
                    /*lda*/ BSZC * DMODELC, /*ldb*/ BSZC * 2 * DMODELC, /*ldc*/ KLENC,
                    /*batch*/ BSZC * NHEADC, /*batch2*/ NHEADC,
                    /*sA1 b*/ DMODELC, /*sA2 n*/ DHEADC,
                    /*sB1 b*/ 2 * DMODELC, /*sB2 n*/ DHEADC,
                    /*sC1 b*/ (long long)NHEADC * QLENC * KLENC,
                    /*sC2 n*/ (long long)QLENC * KLENC);

        // BD_raw[n]: [4096,64] x rk[n]^T[64,1024] -> bd[n]
        launch_gemm(true, 0,
                    qr, rk, bd, nullptr,
                    NT, KLENC, DHEADC,
                    /*lda*/ DMODELC, /*ldb*/ DMODELC, /*ldc*/ KLENC,
                    /*batch*/ NHEADC, /*batch2*/ NHEADC,
                    0, DHEADC, 0, DHEADC, 0, (long long)NT * KLENC);

        // combine AC + shifted BD, mask, scale, softmax (in place in scores)
        softmax_k<<<dim3(QLENC, BSZC * NHEADC), 256>>>(scores, bd);

        // vec[b,n]: prob[512,1024] x v[b,n][1024,64]
        launch_gemm(false, 0,
                    scores, kv + DMODELC, vec, nullptr,
                    QLENC, DHEADC, KLENC,
                    /*lda*/ KLENC, /*ldb*/ BSZC * 2 * DMODELC, /*ldc*/ BSZC * DMODELC,
                    /*batch*/ BSZC * NHEADC, /*batch2*/ NHEADC,
                    /*sA1 b*/ (long long)NHEADC * QLENC * KLENC,
                    /*sA2 n*/ (long long)QLENC * KLENC,
                    /*sB1 b*/ 2 * DMODELC, /*sB2 n*/ DHEADC,
                    /*sC1 b*/ DMODELC, /*sC2 n*/ DHEADC);

        // attn_out = vec @ Wo[l]
        launch_gemm(false, 0, vec, Wo_l, tmp, nullptr, NT, DMODELC, DMODELC,
                    DMODELC, DMODELC, DMODELC);
        // core = LN1(core + attn_out)
        ln_k<<<NT, 256>>>(core, tmp, ln1g + l * DMODELC, ln1b + l * DMODELC,
                          core, nullptr);
        // h1 = relu(core @ W1 + b1)
        launch_gemm(false, 2, core, W1_l, h1, b1_l, NT, DINNERC, DMODELC,
                    DMODELC, DINNERC, DINNERC);
        // ff = h1 @ W2 + b2
        launch_gemm(false, 1, h1, W2_l, tmp, b2_l, NT, DMODELC, DINNERC,
                    DINNERC, DMODELC, DMODELC);
        // core = LN2(core + ff); mems slot l+1 for l<5
        float* memout = (l < NLAYERC - 1) ? (mems_out + (long long)(l + 1) * LSLOT)
                                          : nullptr;
        ln_k<<<NT, 256>>>(core, tmp, ln2g + l * DMODELC, ln2b + l * DMODELC,
                          core, memout);
    }

    // logits = core @ emb_W^T   [4096,32000]
    launch_gemm(true, 0, core, emb_W, logits, nullptr,
                NT, NTOKC, DMODELC, DMODELC, DMODELC, NTOKC);
    // loss
    loss_k<<<NT, 256>>>(logits, target, out);
}

// round 4
// speedup vs baseline: 1.9547x; 1.9547x over previous
#include <cuda_runtime.h>
#include <cuda_bf16.h>
#include <mma.h>
#include <math.h>

using namespace nvcuda;

// ---------------------------------------------------------------------------
// Transformer-XL forward — tf32 tensor-core (wmma) version.
// All GEMMs: tf32 operands (fp32 in memory), fp32 accumulate.
// ---------------------------------------------------------------------------

#define QLENC   512
#define KLENC   1024
#define BSZC    8
#define NHEADC  16
#define DHEADC  64
#define DMODELC 1024
#define DINNERC 4096
#define NTOKC   32000
#define NLAYERC 6
#define NT      4096        // qlen*bsz tokens
#define KT      8192        // klen*bsz tokens

// ------------------------- scratch (device globals) ------------------------
__device__ float g_core[NT * DMODELC];
__device__ float g_xmem[KT * DMODELC];
__device__ float g_q  [NT * DMODELC];
__device__ float g_qw [NT * DMODELC];
__device__ float g_qr [NT * DMODELC];
__device__ float g_kv [KT * 2 * DMODELC];
__device__ float g_rk [KLENC * DMODELC];
__device__ float g_pos[KLENC * DMODELC];
__device__ float g_scores[67108864];   // [b*16+n][512][1024]
__device__ float g_bd    [67108864];   // [n][4096][1024]
__device__ float g_probs [67108864];
__device__ float g_vec[NT * DMODELC];
__device__ float g_tmp[NT * DMODELC];
__device__ float g_h1 [NT * DINNERC];
__device__ float g_logits[131072000];  // [4096][32000]

// ------------------------------- reductions --------------------------------
__device__ __forceinline__ float block_reduce_max(float v) {
    __shared__ float sd[256];
    int tid = threadIdx.x;
    sd[tid] = v; __syncthreads();
    #pragma unroll
    for (int s = 128; s > 0; s >>= 1) {
        if (tid < s) sd[tid] = fmaxf(sd[tid], sd[tid + s]);
        __syncthreads();
    }
    float r = sd[0]; __syncthreads();
    return r;
}
__device__ __forceinline__ float block_reduce_sum(float v) {
    __shared__ float sd[256];
    int tid = threadIdx.x;
    sd[tid] = v; __syncthreads();
    #pragma unroll
    for (int s = 128; s > 0; s >>= 1) {
        if (tid < s) sd[tid] += sd[tid + s];
        __syncthreads();
    }
    float r = sd[0]; __syncthreads();
    return r;
}

// ------------------------------ tf32 wmma GEMM -----------------------------
// C[M,N] = A[M,K]*op(B), fp32 storage, tf32 compute, fp32 accumulate.
// TB: B stored [N,K] row-major (compute with B^T).
// EPI: 0 none, 1 +bias, 2 +bias+relu. Batched: z1=z/batch2, z2=z%batch2.
// Block tile 128x128x32; 8 warps (2x4), warp tile 64x32.
// Requires M%128==0, K%32==0; N handled with guards (cols in steps of 16).
template<bool TB, int EPI>
__global__ void __launch_bounds__(256) wgemm_k(
    const float* __restrict__ A, const float* __restrict__ B,
    float* __restrict__ C, const float* __restrict__ bias,
    int M, int N, int K, int lda, int ldb, int ldc,
    int batch2,
    long long sA1, long long sA2, long long sB1, long long sB2,
    long long sC1, long long sC2)
{
    int z = blockIdx.z;
    int z1 = z / batch2, z2 = z - z1 * batch2;
    A += z1 * sA1 + z2 * sA2;
    B += z1 * sB1 + z2 * sB2;
    C += z1 * sC1 + z2 * sC2;

    __shared__ float As[128 * 36];          // 128 rows x 32 (pad 36)
    __shared__ float Bs[4608];              // TB: 128x36 ; !TB: 32x132(pad 132->use 4224)
    __shared__ float stage[8][256];

    const int tid  = threadIdx.x;
    const int m0   = blockIdx.y * 128, n0 = blockIdx.x * 128;
    const int warp = tid >> 5, lane = tid & 31;
    const int wm   = warp >> 2, wn = warp & 3;

    wmma::fragment<wmma::accumulator, 16, 16, 8, float> acc[4][2];
    #pragma unroll
    for (int i = 0; i < 4; i++)
        #pragma unroll
        for (int j = 0; j < 2; j++)
            wmma::fill_fragment(acc[i][j], 0.f);

    for (int k0 = 0; k0 < K; k0 += 32) {
        // A tile: 128x32 fp32.  256 thr: 4 iters, each thread one float4.
        #pragma unroll
        for (int r = 0; r < 4; r++) {
            int row = r * 32 + (tid >> 3);
            int c4  = (tid & 7) * 4;
            float4 v = *(const float4*)(A + (long long)(m0 + row) * lda + k0 + c4);
            *(float4*)&As[row * 36 + c4] = v;
        }
        if (TB) {
            #pragma unroll
            for (int r = 0; r < 4; r++) {
                int row = r * 32 + (tid >> 3);
                int c4  = (tid & 7) * 4;
                float4 v = *(const float4*)(B + (long long)(n0 + row) * ldb + k0 + c4);
                *(float4*)&Bs[row * 36 + c4] = v;
            }
        } else {
            #pragma unroll
            for (int r = 0; r < 4; r++) {
                int row = r * 8 + (tid >> 5);
                int c4  = (tid & 31) * 4;
                float4 v;
                if (n0 + c4 < N)
                    v = *(const float4*)(B + (long long)(k0 + row) * ldb + n0 + c4);
                else
                    v = make_float4(0.f, 0.f, 0.f, 0.f);
                *(float4*)&Bs[row * 132 + c4] = v;
            }
        }
        __syncthreads();

        #pragma unroll
        for (int kk = 0; kk < 4; kk++) {
            wmma::fragment<wmma::matrix_a, 16, 16, 8, wmma::precision::tf32,
                           wmma::row_major> af[4];
            #pragma unroll
            for (int i = 0; i < 4; i++) {
                wmma::load_matrix_sync(af[i], &As[(wm * 64 + i * 16) * 36 + kk * 8], 36);
                #pragma unroll
                for (int e = 0; e < af[i].num_elements; e++)
                    af[i].x[e] = wmma::__float_to_tf32(af[i].x[e]);
            }
            #pragma unroll
            for (int j = 0; j < 2; j++) {
                if (TB) {
                    wmma::fragment<wmma::matrix_b, 16, 16, 8, wmma::precision::tf32,
                                   wmma::col_major> bfg;
                    wmma::load_matrix_sync(bfg, &Bs[(wn * 32 + j * 16) * 36 + kk * 8], 36);
                    #pragma unroll
                    for (int e = 0; e < bfg.num_elements; e++)
                        bfg.x[e] = wmma::__float_to_tf32(bfg.x[e]);
                    #pragma unroll
                    for (int i = 0; i < 4; i++)
                        wmma::mma_sync(acc[i][j], af[i], bfg, acc[i][j]);
                } else {
                    wmma::fragment<wmma::matrix_b, 16, 16, 8, wmma::precision::tf32,
                                   wmma::row_major> bfg;
                    wmma::load_matrix_sync(bfg, &Bs[(kk * 8) * 132 + wn * 32 + j * 16], 132);
                    #pragma unroll
                    for (int e = 0; e < bfg.num_elements; e++)
                        bfg.x[e] = wmma::__float_to_tf32(bfg.x[e]);
                    #pragma unroll
                    for (int i = 0; i < 4; i++)
                        wmma::mma_sync(acc[i][j], af[i], bfg, acc[i][j]);
                }
            }
        }
        __syncthreads();
    }

    if (EPI == 0) {
        #pragma unroll
        for (int i = 0; i < 4; i++)
            #pragma unroll
            for (int j = 0; j < 2; j++) {
                int row0 = m0 + wm * 64 + i * 16;
                int col0 = n0 + wn * 32 + j * 16;
                if (col0 < N)
                    wmma::store_matrix_sync(C + (long long)row0 * ldc + col0,
                                            acc[i][j], ldc, wmma::mem_row_major);
            }
    } else {
        float* st = &stage[warp][0];
        #pragma unroll
        for (int i = 0; i < 4; i++)
            #pragma unroll
            for (int j = 0; j < 2; j++) {
                int row0 = m0 + wm * 64 + i * 16;
                int col0 = n0 + wn * 32 + j * 16;
                if (col0 < N) {
                    wmma::store_matrix_sync(st, acc[i][j], 16, wmma::mem_row_major);
                    __syncwarp();
                    #pragma unroll
                    for (int e = 0; e < 8; e++) {
                        int idx = lane * 8 + e;
                        int r = idx >> 4, c = idx & 15;
                        float v = st[idx];
                        int col = col0 + c;
                        if (EPI >= 1) v += bias[col];
                        if (EPI == 2) v = fmaxf(v, 0.f);
                        C[(long long)(row0 + r) * ldc + col] = v;
                    }
                    __syncwarp();
                }
            }
    }
}

// ------------------------------ small kernels ------------------------------
__global__ void embed_k(const int* __restrict__ data, const float* __restrict__ emb,
                        float* __restrict__ core, float* __restrict__ memout)
{
    int t = blockIdx.x;
    int tok = data[t];
    const float* src = emb + (long long)tok * DMODELC;
    #pragma unroll
    for (int r = 0; r < 4; r++) {
        int d = threadIdx.x + 256 * r;
        float v = src[d];
        core[(long long)t * DMODELC + d]   = v;
        memout[(long long)t * DMODELC + d] = v;
    }
}

__global__ void pos_k(float* __restrict__ pos)
{
    int k = blockIdx.x;
    float p = (float)(KLENC - 1 - k);
    #pragma unroll
    for (int r = 0; r < 4; r++) {
        int c = threadIdx.x + 256 * r;
        int j = (c < 512) ? c : (c - 512);
        float invf = 1.0f / powf(10000.0f, (2.0f * (float)j) / 1024.0f);
        float ang = p * invf;
        pos[(long long)k * DMODELC + c] = (c < 512) ? sinf(ang) : cosf(ang);
    }
}

__global__ void qwqr_k(const float* __restrict__ q, const float* __restrict__ rwb,
                       const float* __restrict__ rrb,
                       float* __restrict__ qw, float* __restrict__ qr)
{
    long long idx = (long long)blockIdx.x * 256 + threadIdx.x;
    int c = (int)(idx & 1023);
    float v = q[idx];
    qw[idx] = v + rwb[c];
    qr[idx] = v + rrb[c];
}

// score = (AC[i,j] + BD_raw[i, j+511-i]) * 0.125 for j <= i+512 else -inf;
// softmax over j; write fp32 probs.
__global__ void softmax_k(const float* __restrict__ scores, const float* __restrict__ bd,
                          float* __restrict__ probs)
{
    int i  = blockIdx.x;
    int bn = blockIdx.y;
    int b = bn >> 4, n = bn & 15;
    const float* ac = scores + (long long)bn * (QLENC * KLENC) + (long long)i * KLENC;
    float* pr = probs + (long long)bn * (QLENC * KLENC) + (long long)i * KLENC;
    const float* bdr = bd + (long long)n * ((long long)NT * KLENC)
                          + (long long)(i * BSZC + b) * KLENC;
    int shift = QLENC - 1 - i;
    int lim = i + 512;

    float vals[4];
    float lmax = -1e30f;
    #pragma unroll
    for (int r = 0; r < 4; r++) {
        int j = threadIdx.x + 256 * r;
        float v = -1e30f;
        if (j <= lim) v = (ac[j] + bdr[j + shift]) * 0.125f;
        vals[r] = v;
        lmax = fmaxf(lmax, v);
    }
    float rmax = block_reduce_max(lmax);
    float lsum = 0.f;
    #pragma unroll
    for (int r = 0; r < 4; r++) {
        float e = expf(vals[r] - rmax);
        vals[r] = e;
        lsum += e;
    }
    float rsum = block_reduce_sum(lsum);
    float inv = 1.0f / rsum;
    #pragma unroll
    for (int r = 0; r < 4; r++) {
        int j = threadIdx.x + 256 * r;
        pr[j] = vals[r] * inv;
    }
}

// dst = LayerNorm(x + res); optionally fp32 copy (mems)
__global__ void ln_k(const float* __restrict__ x, const float* __restrict__ res,
                     const float* __restrict__ g, const float* __restrict__ bb,
                     float* __restrict__ dst, float* __restrict__ dst2)
{
    long long t = blockIdx.x;
    const float* xr = x   + t * DMODELC;
    const float* rr = res + t * DMODELC;
    float v[4];
    float s = 0.f, sq = 0.f;
    #pragma unroll
    for (int r = 0; r < 4; r++) {
        int d = threadIdx.x + 256 * r;
        float u = xr[d] + rr[d];
        v[r] = u; s += u; sq += u * u;
    }
    float sum  = block_reduce_sum(s);
    float sums = block_reduce_sum(sq);
    float mean = sum * (1.0f / 1024.0f);
    float var  = sums * (1.0f / 1024.0f) - mean * mean;
    float rstd = rsqrtf(var + 1e-5f);
    #pragma unroll
    for (int r = 0; r < 4; r++) {
        int d = threadIdx.x + 256 * r;
        float y = (v[r] - mean) * rstd * g[d] + bb[d];
        dst[t * DMODELC + d] = y;
        if (dst2) dst2[t * DMODELC + d] = y;
    }
}

__global__ void loss_k(const float* __restrict__ logits, const int* __restrict__ target,
                       float* __restrict__ out)
{
    int t = blockIdx.x;
    const float* lr = logits + (long long)t * NTOKC;
    float lmax = -1e30f;
    for (int j = threadIdx.x; j < NTOKC; j += 256) lmax = fmaxf(lmax, lr[j]);
    float m = block_reduce_max(lmax);
    float lsum = 0.f;
    for (int j = threadIdx.x; j < NTOKC; j += 256) lsum += expf(lr[j] - m);
    float s = block_reduce_sum(lsum);
    if (threadIdx.x == 0) {
        int tg = target[t];
        out[t] = -(lr[tg] - m - logf(s));
    }
}

// ------------------------------ host dispatch ------------------------------
extern "C" void kernel_launch(void* const* d_in, const int* in_sizes, int n_in,
                              void* d_out, int out_size)
{
    const int*   data   = (const int*)  d_in[0];
    const int*   target = (const int*)  d_in[1];
    const float* memory = (const float*)d_in[2];
    const float* emb_W  = (const float*)d_in[3];
    const float* rwb    = (const float*)d_in[4];
    const float* rrb    = (const float*)d_in[5];
    const float* Wq     = (const float*)d_in[6];
    const float* Wkv    = (const float*)d_in[7];
    const float* Wr     = (const float*)d_in[8];
    const float* Wo     = (const float*)d_in[9];
    const float* W1     = (const float*)d_in[10];
    const float* b1     = (const float*)d_in[11];
    const float* W2     = (const float*)d_in[12];
    const float* b2     = (const float*)d_in[13];
    const float* ln1g   = (const float*)d_in[14];
    const float* ln1b   = (const float*)d_in[15];
    const float* ln2g   = (const float*)d_in[16];
    const float* ln2b   = (const float*)d_in[17];
    float* out = (float*)d_out;

    float *core, *xmem, *q, *qw, *qr, *kv, *rk, *pos, *scores, *bdp, *probs,
          *vec, *tmp, *h1, *logits;
    cudaGetSymbolAddress((void**)&core,   g_core);
    cudaGetSymbolAddress((void**)&xmem,   g_xmem);
    cudaGetSymbolAddress((void**)&q,      g_q);
    cudaGetSymbolAddress((void**)&qw,     g_qw);
    cudaGetSymbolAddress((void**)&qr,     g_qr);
    cudaGetSymbolAddress((void**)&kv,     g_kv);
    cudaGetSymbolAddress((void**)&rk,     g_rk);
    cudaGetSymbolAddress((void**)&pos,    g_pos);
    cudaGetSymbolAddress((void**)&scores, g_scores);
    cudaGetSymbolAddress((void**)&bdp,    g_bd);
    cudaGetSymbolAddress((void**)&probs,  g_probs);
    cudaGetSymbolAddress((void**)&vec,    g_vec);
    cudaGetSymbolAddress((void**)&tmp,    g_tmp);
    cudaGetSymbolAddress((void**)&h1,     g_h1);
    cudaGetSymbolAddress((void**)&logits, g_logits);

    const long long LSLOT = (long long)NT * DMODELC;
    float* mems_out = out + NT;

    embed_k<<<NT, 256>>>(data, emb_W, core, mems_out);
    pos_k<<<KLENC, 256>>>(pos);

    for (int l = 0; l < NLAYERC; l++) {
        const float* Wq_l  = Wq  + (long long)l * DMODELC * DMODELC;
        const float* Wkv_l = Wkv + (long long)l * DMODELC * 2 * DMODELC;
        const float* Wr_l  = Wr  + (long long)l * DMODELC * DMODELC;
        const float* Wo_l  = Wo  + (long long)l * DMODELC * DMODELC;
        const float* W1_l  = W1  + (long long)l * DMODELC * DINNERC;
        const float* b1_l  = b1  + (long long)l * DINNERC;
        const float* W2_l  = W2  + (long long)l * DINNERC * DMODELC;
        const float* b2_l  = b2  + (long long)l * DMODELC;

        // x_mem = [memory[l]; core]
        cudaMemcpyAsync(xmem, memory + (long long)l * LSLOT, LSLOT * sizeof(float),
                        cudaMemcpyDeviceToDevice, 0);
        cudaMemcpyAsync(xmem + LSLOT, core, LSLOT * sizeof(float),
                        cudaMemcpyDeviceToDevice, 0);

        // q = core @ Wq
        wgemm_k<false, 0><<<dim3(DMODELC / 128, NT / 128, 1), 256>>>(
            core, Wq_l, q, nullptr, NT, DMODELC, DMODELC,
            DMODELC, DMODELC, DMODELC, 1, 0, 0, 0, 0, 0, 0);
        qwqr_k<<<(NT * DMODELC) / 256, 256>>>(q, rwb, rrb, qw, qr);

        // kv = xmem @ Wkv
        wgemm_k<false, 0><<<dim3(2 * DMODELC / 128, KT / 128, 1), 256>>>(
            xmem, Wkv_l, kv, nullptr, KT, 2 * DMODELC, DMODELC,
            DMODELC, 2 * DMODELC, 2 * DMODELC, 1, 0, 0, 0, 0, 0, 0);

        // r_k = pos @ Wr
        wgemm_k<false, 0><<<dim3(DMODELC / 128, KLENC / 128, 1), 256>>>(
            pos, Wr_l, rk, nullptr, KLENC, DMODELC, DMODELC,
            DMODELC, DMODELC, DMODELC, 1, 0, 0, 0, 0, 0, 0);

        // AC[b,n] = qw[512,64] @ k^T
        wgemm_k<true, 0><<<dim3(KLENC / 128, QLENC / 128, BSZC * NHEADC), 256>>>(
            qw, kv, scores, nullptr, QLENC, KLENC, DHEADC,
            BSZC * DMODELC, BSZC * 2 * DMODELC, KLENC,
            NHEADC,
            DMODELC, DHEADC,
            2 * DMODELC, DHEADC,
            (long long)NHEADC * QLENC * KLENC, (long long)QLENC * KLENC);

        // BD_raw[n] = qr[4096,64] @ rk^T
        wgemm_k<true, 0><<<dim3(KLENC / 128, NT / 128, NHEADC), 256>>>(
            qr, rk, bdp, nullptr, NT, KLENC, DHEADC,
            DMODELC, DMODELC, KLENC,
            NHEADC,
            0, DHEADC, 0, DHEADC, 0, (long long)NT * KLENC);

        softmax_k<<<dim3(QLENC, BSZC * NHEADC), 256>>>(scores, bdp, probs);

        // vec[b,n] = probs[512,1024] @ v[1024,64]
        wgemm_k<false, 0><<<dim3(1, QLENC / 128, BSZC * NHEADC), 256>>>(
            probs, kv + DMODELC, vec, nullptr, QLENC, DHEADC, KLENC,
            KLENC, BSZC * 2 * DMODELC, BSZC * DMODELC,
            NHEADC,
            (long long)NHEADC * QLENC * KLENC, (long long)QLENC * KLENC,
            2 * DMODELC, DHEADC,
            DMODELC, DHEADC);

        // attn_out = vec @ Wo
        wgemm_k<false, 0><<<dim3(DMODELC / 128, NT / 128, 1), 256>>>(
            vec, Wo_l, tmp, nullptr, NT, DMODELC, DMODELC,
            DMODELC, DMODELC, DMODELC, 1, 0, 0, 0, 0, 0, 0);

        ln_k<<<NT, 256>>>(core, tmp, ln1g + l * DMODELC, ln1b + l * DMODELC,
                          core, nullptr);

        // h1 = relu(core @ W1 + b1)
        wgemm_k<false, 2><<<dim3(DINNERC / 128, NT / 128, 1), 256>>>(
            core, W1_l, h1, b1_l, NT, DINNERC, DMODELC,
            DMODELC, DINNERC, DINNERC, 1, 0, 0, 0, 0, 0, 0);

        // ff = h1 @ W2 + b2
        wgemm_k<false, 1><<<dim3(DMODELC / 128, NT / 128, 1), 256>>>(
            h1, W2_l, tmp, b2_l, NT, DMODELC, DINNERC,
            DINNERC, DMODELC, DMODELC, 1, 0, 0, 0, 0, 0, 0);

        float* memout = (l < NLAYERC - 1) ? (mems_out + (long long)(l + 1) * LSLOT)
                                          : nullptr;
        ln_k<<<NT, 256>>>(core, tmp, ln2g + l * DMODELC, ln2b + l * DMODELC,
                          core, memout);
    }

    // logits = core @ emb_W^T   [4096,32000]
    wgemm_k<true, 0><<<dim3(NTOKC / 128, NT / 128, 1), 256>>>(
        core, emb_W, logits, nullptr, NT, NTOKC, DMODELC,
        DMODELC, DMODELC, NTOKC, 1, 0, 0, 0, 0, 0, 0);

    loss_k<<<NT, 256>>>(logits, target, out);
}

// round 5
// speedup vs baseline: 3.1884x; 1.6311x over previous
#include <cuda_runtime.h>
#include <cuda_bf16.h>
#include <mma.h>
#include <math.h>

using namespace nvcuda;

// ---------------------------------------------------------------------------
// Transformer-XL forward — tf32 tensor-core GEMMs with cp.async double
// buffering; bf16 logits GEMM (loss-only path); fp32 softmax/LN/loss.
// ---------------------------------------------------------------------------

#define QLENC   512
#define KLENC   1024
#define BSZC    8
#define NHEADC  16
#define DHEADC  64
#define DMODELC 1024
#define DINNERC 4096
#define NTOKC   32000
#define NLAYERC 6
#define NT      4096
#define KT      8192

typedef __nv_bfloat16 bf;

// ------------------------- scratch (device globals) ------------------------
__device__ float g_core[NT * DMODELC];
__device__ float g_xmem[KT * DMODELC];
__device__ float g_q  [NT * DMODELC];
__device__ float g_qw [NT * DMODELC];
__device__ float g_qr [NT * DMODELC];
__device__ float g_kv [KT * 2 * DMODELC];
__device__ float g_rk [KLENC * DMODELC];
__device__ float g_pos[KLENC * DMODELC];
__device__ float g_scores[67108864];   // [b*16+n][512][1024]
__device__ float g_bd    [67108864];   // [n][4096][1024]
__device__ float g_probs [67108864];
__device__ float g_vec[NT * DMODELC];
__device__ float g_tmp[NT * DMODELC];
__device__ float g_h1 [NT * DINNERC];
__device__ float g_logits[131072000];  // [4096][32000]
__device__ bf    g_embb [NTOKC * DMODELC];
__device__ bf    g_coreb[NT * DMODELC];

// ------------------------------ cp.async helpers ---------------------------
__device__ __forceinline__ void cp16(void* dst, const void* src) {
    unsigned d = (unsigned)__cvta_generic_to_shared(dst);
    asm volatile("cp.async.cg.shared.global [%0], [%1], 16;\n" :: "r"(d), "l"(src));
}
__device__ __forceinline__ void cp_commit() { asm volatile("cp.async.commit_group;\n"); }
__device__ __forceinline__ void cp_wait0()  { asm volatile("cp.async.wait_group 0;\n"); }

// ------------------------------- reductions --------------------------------
__device__ __forceinline__ float block_reduce_max(float v) {
    __shared__ float sd[256];
    int tid = threadIdx.x;
    sd[tid] = v; __syncthreads();
    #pragma unroll
    for (int s = 128; s > 0; s >>= 1) {
        if (tid < s) sd[tid] = fmaxf(sd[tid], sd[tid + s]);
        __syncthreads();
    }
    float r = sd[0]; __syncthreads();
    return r;
}
__device__ __forceinline__ float block_reduce_sum(float v) {
    __shared__ float sd[256];
    int tid = threadIdx.x;
    sd[tid] = v; __syncthreads();
    #pragma unroll
    for (int s = 128; s > 0; s >>= 1) {
        if (tid < s) sd[tid] += sd[tid + s];
        __syncthreads();
    }
    float r = sd[0]; __syncthreads();
    return r;
}

// --------------------- tf32 double-buffered wmma GEMM ----------------------
// C[128*gy, BN*gx] = A*op(B), fp32 storage, tf32 compute.
// TB: B stored [N,K] (compute with B^T). EPI: 0 none, 1 +bias, 2 +bias+relu.
// Exact tiling required: M%128==0, N%BN==0, K%32==0.
template<int BN, bool TB, int EPI>
__global__ void __launch_bounds__(256) tgemm_k(
    const float* __restrict__ A, const float* __restrict__ B,
    float* __restrict__ C, const float* __restrict__ bias,
    int K, int lda, int ldb, int ldc,
    int batch2,
    long long sA1, long long sA2, long long sB1, long long sB2,
    long long sC1, long long sC2)
{
    constexpr int WARPS_N = BN / 32;         // 4 or 2
    constexpr int WARPS_M = 8 / WARPS_N;     // 2 or 4
    constexpr int MI = 128 / (WARPS_M * 16); // 4 or 2
    constexpr int NI = 2;
    constexpr int A_LD  = 36;
    constexpr int A_ELE = 128 * A_LD;
    constexpr int B_LD  = TB ? 36 : (BN + 4);
    constexpr int B_ELE = TB ? (BN * 36) : (32 * (BN + 4));

    int z = blockIdx.z;
    int z1 = z / batch2, z2 = z - z1 * batch2;
    A += z1 * sA1 + z2 * sA2;
    B += z1 * sB1 + z2 * sB2;
    C += z1 * sC1 + z2 * sC2;

    extern __shared__ float smem[];
    float* sA[2] = { smem, smem + A_ELE };
    float* sB[2] = { smem + 2 * A_ELE, smem + 2 * A_ELE + B_ELE };
    float* stage = smem + 2 * A_ELE + 2 * B_ELE;

    const int tid  = threadIdx.x;
    const int m0   = blockIdx.y * 128, n0 = blockIdx.x * BN;
    const int warp = tid >> 5, lane = tid & 31;
    const int wm   = warp / WARPS_N, wn = warp % WARPS_N;
    const int wmB  = wm * MI * 16, wnB = wn * 32;

    wmma::fragment<wmma::accumulator, 16, 16, 8, float> acc[MI][NI];
    #pragma unroll
    for (int i = 0; i < MI; i++)
        #pragma unroll
        for (int j = 0; j < NI; j++)
            wmma::fill_fragment(acc[i][j], 0.f);

    auto loadA = [&](int buf, int k0) {
        #pragma unroll
        for (int p = 0; p < 4; p++) {
            int row = p * 32 + (tid >> 3), col = (tid & 7) * 4;
            cp16(&sA[buf][row * A_LD + col],
                 A + (long long)(m0 + row) * lda + k0 + col);
        }
    };
    auto loadB = [&](int buf, int k0) {
        if (TB) {
            #pragma unroll
            for (int p = 0; p < BN / 32; p++) {
                int row = p * 32 + (tid >> 3), col = (tid & 7) * 4;
                cp16(&sB[buf][row * B_LD + col],
                     B + (long long)(n0 + row) * ldb + k0 + col);
            }
        } else {
            constexpr int TPR = BN / 4;        // threads per row
            constexpr int RPP = 256 / TPR;     // rows per pass
            #pragma unroll
            for (int p = 0; p < 32 / RPP; p++) {
                int row = p * RPP + tid / TPR;
                int col = (tid % TPR) * 4;
                cp16(&sB[buf][row * B_LD + col],
                     B + (long long)(k0 + row) * ldb + n0 + col);
            }
        }
    };
    auto compute = [&](int buf) {
        #pragma unroll
        for (int kk = 0; kk < 4; kk++) {
            wmma::fragment<wmma::matrix_a, 16, 16, 8, wmma::precision::tf32,
                           wmma::row_major> af[MI];
            #pragma unroll
            for (int i = 0; i < MI; i++) {
                wmma::load_matrix_sync(af[i],
                    &sA[buf][(wmB + i * 16) * A_LD + kk * 8], A_LD);
                #pragma unroll
                for (int e = 0; e < af[i].num_elements; e++)
                    af[i].x[e] = wmma::__float_to_tf32(af[i].x[e]);
            }
            #pragma unroll
            for (int j = 0; j < NI; j++) {
                if (TB) {
                    wmma::fragment<wmma::matrix_b, 16, 16, 8, wmma::precision::tf32,
                                   wmma::col_major> bfg;
                    wmma::load_matrix_sync(bfg,
                        &sB[buf][(wnB + j * 16) * B_LD + kk * 8], B_LD);
                    #pragma unroll
                    for (int e = 0; e < bfg.num_elements; e++)
                        bfg.x[e] = wmma::__float_to_tf32(bfg.x[e]);
                    #pragma unroll
                    for (int i = 0; i < MI; i++)
                        wmma::mma_sync(acc[i][j], af[i], bfg, acc[i][j]);
                } else {
                    wmma::fragment<wmma::matrix_b, 16, 16, 8, wmma::precision::tf32,
                                   wmma::row_major> bfg;
                    wmma::load_matrix_sync(bfg,
                        &sB[buf][(kk * 8) * B_LD + wnB + j * 16], B_LD);
                    #pragma unroll
                    for (int e = 0; e < bfg.num_elements; e++)
                        bfg.x[e] = wmma::__float_to_tf32(bfg.x[e]);
                    #pragma unroll
                    for (int i = 0; i < MI; i++)
                        wmma::mma_sync(acc[i][j], af[i], bfg, acc[i][j]);
                }
            }
        }
    };

    int buf = 0;
    loadA(0, 0); loadB(0, 0); cp_commit();
    for (int k0 = 0; k0 < K; k0 += 32) {
        cp_wait0();
        __syncthreads();
        int nk = k0 + 32;
        if (nk < K) { loadA(buf ^ 1, nk); loadB(buf ^ 1, nk); }
        cp_commit();
        compute(buf);
        buf ^= 1;
    }

    if (EPI == 0) {
        #pragma unroll
        for (int i = 0; i < MI; i++)
            #pragma unroll
            for (int j = 0; j < NI; j++) {
                int row0 = m0 + wmB + i * 16;
                int col0 = n0 + wnB + j * 16;
                wmma::store_matrix_sync(C + (long long)row0 * ldc + col0,
                                        acc[i][j], ldc, wmma::mem_row_major);
            }
    } else {
        float* st = stage + warp * 256;
        #pragma unroll
        for (int i = 0; i < MI; i++)
            #pragma unroll
            for (int j = 0; j < NI; j++) {
                int row0 = m0 + wmB + i * 16;
                int col0 = n0 + wnB + j * 16;
                wmma::store_matrix_sync(st, acc[i][j], 16, wmma::mem_row_major);
                __syncwarp();
                #pragma unroll
                for (int e = 0; e < 8; e++) {
                    int idx = lane * 8 + e;
                    int r = idx >> 4, c = idx & 15;
                    float v = st[idx];
                    int col = col0 + c;
                    if (EPI >= 1) v += bias[col];
                    if (EPI == 2) v = fmaxf(v, 0.f);
                    C[(long long)(row0 + r) * ldc + col] = v;
                }
                __syncwarp();
            }
    }
}

// ------------------ bf16 double-buffered GEMM (B^T), fp32 out --------------
// C[128*gy, 128*gx] = A[M,K] * B^T, A,B bf16 K-contiguous. Used for logits.
__global__ void __launch_bounds__(256) bgemm_k(
    const bf* __restrict__ A, const bf* __restrict__ B, float* __restrict__ C,
    int K, int lda, int ldb, int ldc)
{
    __shared__ bf sA[2][128 * 40];
    __shared__ bf sB[2][128 * 40];

    const int tid  = threadIdx.x;
    const int m0   = blockIdx.y * 128, n0 = blockIdx.x * 128;
    const int warp = tid >> 5;
    const int wm   = warp >> 2, wn = warp & 3;
    const int wmB  = wm * 64, wnB = wn * 32;

    wmma::fragment<wmma::accumulator, 16, 16, 16, float> acc[4][2];
    #pragma unroll
    for (int i = 0; i < 4; i++)
        #pragma unroll
        for (int j = 0; j < 2; j++)
            wmma::fill_fragment(acc[i][j], 0.f);

    auto loadAB = [&](int buf, int k0) {
        #pragma unroll
        for (int p = 0; p < 2; p++) {
            int row = p * 64 + (tid >> 2), col = (tid & 3) * 8;
            cp16(&sA[buf][row * 40 + col],
                 A + (long long)(m0 + row) * lda + k0 + col);
            cp16(&sB[buf][row * 40 + col],
                 B + (long long)(n0 + row) * ldb + k0 + col);
        }
    };
    auto compute = [&](int buf) {
        #pragma unroll
        for (int kk = 0; kk < 2; kk++) {
            wmma::fragment<wmma::matrix_a, 16, 16, 16, bf, wmma::row_major> af[4];
            #pragma unroll
            for (int i = 0; i < 4; i++)
                wmma::load_matrix_sync(af[i], &sA[buf][(wmB + i * 16) * 40 + kk * 16], 40);
            #pragma unroll
            for (int j = 0; j < 2; j++) {
                wmma::fragment<wmma::matrix_b, 16, 16, 16, bf, wmma::col_major> bfg;
                wmma::load_matrix_sync(bfg, &sB[buf][(wnB + j * 16) * 40 + kk * 16], 40);
                #pragma unroll
                for (int i = 0; i < 4; i++)
                    wmma::mma_sync(acc[i][j], af[i], bfg, acc[i][j]);
            }
        }
    };

    int buf = 0;
    loadAB(0, 0); cp_commit();
    for (int k0 = 0; k0 < K; k0 += 32) {
        cp_wait0();
        __syncthreads();
        int nk = k0 + 32;
        if (nk < K) loadAB(buf ^ 1, nk);
        cp_commit();
        compute(buf);
        buf ^= 1;
    }

    #pragma unroll
    for (int i = 0; i < 4; i++)
        #pragma unroll
        for (int j = 0; j < 2; j++) {
            int row0 = m0 + wmB + i * 16;
            int col0 = n0 + wnB + j * 16;
            wmma::store_matrix_sync(C + (long long)row0 * ldc + col0,
                                    acc[i][j], ldc, wmma::mem_row_major);
        }
}

// ------------------------------ small kernels ------------------------------
__global__ void conv_k(const float* __restrict__ src, bf* __restrict__ dst, int n)
{
    int i = (blockIdx.x * 256 + threadIdx.x) * 4;
    if (i < n) {
        float4 v = *(const float4*)(src + i);
        dst[i + 0] = __float2bfloat16_rn(v.x);
        dst[i + 1] = __float2bfloat16_rn(v.y);
        dst[i + 2] = __float2bfloat16_rn(v.z);
        dst[i + 3] = __float2bfloat16_rn(v.w);
    }
}

__global__ void embed_k(const int* __restrict__ data, const float* __restrict__ emb,
                        float* __restrict__ core, float* __restrict__ memout)
{
    int t = blockIdx.x;
    int tok = data[t];
    const float* src = emb + (long long)tok * DMODELC;
    #pragma unroll
    for (int r = 0; r < 4; r++) {
        int d = threadIdx.x + 256 * r;
        float v = src[d];
        core[(long long)t * DMODELC + d]   = v;
        memout[(long long)t * DMODELC + d] = v;
    }
}

__global__ void pos_k(float* __restrict__ pos)
{
    int k = blockIdx.x;
    float p = (float)(KLENC - 1 - k);
    #pragma unroll
    for (int r = 0; r < 4; r++) {
        int c = threadIdx.x + 256 * r;
        int j = (c < 512) ? c : (c - 512);
        float invf = 1.0f / powf(10000.0f, (2.0f * (float)j) / 1024.0f);
        float ang = p * invf;
        pos[(long long)k * DMODELC + c] = (c < 512) ? sinf(ang) : cosf(ang);
    }
}

__global__ void qwqr_k(const float* __restrict__ q, const float* __restrict__ rwb,
                       const float* __restrict__ rrb,
                       float* __restrict__ qw, float* __restrict__ qr)
{
    long long idx = (long long)blockIdx.x * 256 + threadIdx.x;
    int c = (int)(idx & 1023);
    float v = q[idx];
    qw[idx] = v + rwb[c];
    qr[idx] = v + rrb[c];
}

__global__ void softmax_k(const float* __restrict__ scores, const float* __restrict__ bd,
                          float* __restrict__ probs)
{
    int i  = blockIdx.x;
    int bn = blockIdx.y;
    int b = bn >> 4, n = bn & 15;
    const float* ac = scores + (long long)bn * (QLENC * KLENC) + (long long)i * KLENC;
    float* pr = probs + (long long)bn * (QLENC * KLENC) + (long long)i * KLENC;
    const float* bdr = bd + (long long)n * ((long long)NT * KLENC)
                          + (long long)(i * BSZC + b) * KLENC;
    int shift = QLENC - 1 - i;
    int lim = i + 512;

    float vals[4];
    float lmax = -1e30f;
    #pragma unroll
    for (int r = 0; r < 4; r++) {
        int j = threadIdx.x + 256 * r;
        float v = -1e30f;
        if (j <= lim) v = (ac[j] + bdr[j + shift]) * 0.125f;
        vals[r] = v;
        lmax = fmaxf(lmax, v);
    }
    float rmax = block_reduce_max(lmax);
    float lsum = 0.f;
    #pragma unroll
    for (int r = 0; r < 4; r++) {
        float e = expf(vals[r] - rmax);
        vals[r] = e;
        lsum += e;
    }
    float rsum = block_reduce_sum(lsum);
    float inv = 1.0f / rsum;
    #pragma unroll
    for (int r = 0; r < 4; r++) {
        int j = threadIdx.x + 256 * r;
        pr[j] = vals[r] * inv;
    }
}

__global__ void ln_k(const float* __restrict__ x, const float* __restrict__ res,
                     const float* __restrict__ g, const float* __restrict__ bb,
                     float* __restrict__ dst, float* __restrict__ dst2)
{
    long long t = blockIdx.x;
    const float* xr = x   + t * DMODELC;
    const float* rr = res + t * DMODELC;
    float v[4];
    float s = 0.f, sq = 0.f;
    #pragma unroll
    for (int r = 0; r < 4; r++) {
        int d = threadIdx.x + 256 * r;
        float u = xr[d] + rr[d];
        v[r] = u; s += u; sq += u * u;
    }
    float sum  = block_reduce_sum(s);
    float sums = block_reduce_sum(sq);
    float mean = sum * (1.0f / 1024.0f);
    float var  = sums * (1.0f / 1024.0f) - mean * mean;
    float rstd = rsqrtf(var + 1e-5f);
    #pragma unroll
    for (int r = 0; r < 4; r++) {
        int d = threadIdx.x + 256 * r;
        float y = (v[r] - mean) * rstd * g[d] + bb[d];
        dst[t * DMODELC + d] = y;
        if (dst2) dst2[t * DMODELC + d] = y;
    }
}

__global__ void loss_k(const float* __restrict__ logits, const int* __restrict__ target,
                       float* __restrict__ out)
{
    int t = blockIdx.x;
    const float* lr = logits + (long long)t * NTOKC;
    float lmax = -1e30f;
    for (int j = threadIdx.x; j < NTOKC; j += 256) lmax = fmaxf(lmax, lr[j]);
    float m = block_reduce_max(lmax);
    float lsum = 0.f;
    for (int j = threadIdx.x; j < NTOKC; j += 256) lsum += expf(lr[j] - m);
    float s = block_reduce_sum(lsum);
    if (threadIdx.x == 0) {
        int tg = target[t];
        out[t] = -(lr[tg] - m - logf(s));
    }
}

// ------------------------------ host dispatch ------------------------------
template<int BN, bool TB, int EPI>
static inline void launch_tg(const float* A, const float* B, float* C,
    const float* bias, int gx, int gy, int gz,
    int K, int lda, int ldb, int ldc,
    int batch2 = 1,
    long long sA1 = 0, long long sA2 = 0,
    long long sB1 = 0, long long sB2 = 0,
    long long sC1 = 0, long long sC2 = 0)
{
    const int A_ELE = 128 * 36;
    const int B_ELE = TB ? (BN * 36) : (32 * (BN + 4));
    int smem = (2 * A_ELE + 2 * B_ELE + 2048) * 4;
    cudaFuncSetAttribute(tgemm_k<BN, TB, EPI>,
                         cudaFuncAttributeMaxDynamicSharedMemorySize, smem);
    tgemm_k<BN, TB, EPI><<<dim3(gx, gy, gz), 256, smem>>>(
        A, B, C, bias, K, lda, ldb, ldc, batch2, sA1, sA2, sB1, sB2, sC1, sC2);
}

extern "C" void kernel_launch(void* const* d_in, const int* in_sizes, int n_in,
                              void* d_out, int out_size)
{
    const int*   data   = (const int*)  d_in[0];
    const int*   target = (const int*)  d_in[1];
    const float* memory = (const float*)d_in[2];
    const float* emb_W  = (const float*)d_in[3];
    const float* rwb    = (const float*)d_in[4];
    const float* rrb    = (const float*)d_in[5];
    const float* Wq     = (const float*)d_in[6];
    const float* Wkv    = (const float*)d_in[7];
    const float* Wr     = (const float*)d_in[8];
    const float* Wo     = (const float*)d_in[9];
    const float* W1     = (const float*)d_in[10];
    const float* b1     = (const float*)d_in[11];
    const float* W2     = (const float*)d_in[12];
    const float* b2     = (const float*)d_in[13];
    const float* ln1g   = (const float*)d_in[14];
    const float* ln1b   = (const float*)d_in[15];
    const float* ln2g   = (const float*)d_in[16];
    const float* ln2b   = (const float*)d_in[17];
    float* out = (float*)d_out;

    float *core, *xmem, *q, *qw, *qr, *kv, *rk, *pos, *scores, *bdp, *probs,
          *vec, *tmp, *h1, *logits;
    bf *embb, *coreb;
    cudaGetSymbolAddress((void**)&core,   g_core);
    cudaGetSymbolAddress((void**)&xmem,   g_xmem);
    cudaGetSymbolAddress((void**)&q,      g_q);
    cudaGetSymbolAddress((void**)&qw,     g_qw);
    cudaGetSymbolAddress((void**)&qr,     g_qr);
    cudaGetSymbolAddress((void**)&kv,     g_kv);
    cudaGetSymbolAddress((void**)&rk,     g_rk);
    cudaGetSymbolAddress((void**)&pos,    g_pos);
    cudaGetSymbolAddress((void**)&scores, g_scores);
    cudaGetSymbolAddress((void**)&bdp,    g_bd);
    cudaGetSymbolAddress((void**)&probs,  g_probs);
    cudaGetSymbolAddress((void**)&vec,    g_vec);
    cudaGetSymbolAddress((void**)&tmp,    g_tmp);
    cudaGetSymbolAddress((void**)&h1,     g_h1);
    cudaGetSymbolAddress((void**)&logits, g_logits);
    cudaGetSymbolAddress((void**)&embb,   g_embb);
    cudaGetSymbolAddress((void**)&coreb,  g_coreb);

    const long long LSLOT = (long long)NT * DMODELC;
    float* mems_out = out + NT;

    embed_k<<<NT, 256>>>(data, emb_W, core, mems_out);
    pos_k<<<KLENC, 256>>>(pos);
    conv_k<<<(NTOKC * DMODELC) / 1024, 256>>>(emb_W, embb, NTOKC * DMODELC);

    for (int l = 0; l < NLAYERC; l++) {
        const float* Wq_l  = Wq  + (long long)l * DMODELC * DMODELC;
        const float* Wkv_l = Wkv + (long long)l * DMODELC * 2 * DMODELC;
        const float* Wr_l  = Wr  + (long long)l * DMODELC * DMODELC;
        const float* Wo_l  = Wo  + (long long)l * DMODELC * DMODELC;
        const float* W1_l  = W1  + (long long)l * DMODELC * DINNERC;
        const float* b1_l  = b1  + (long long)l * DINNERC;
        const float* W2_l  = W2  + (long long)l * DINNERC * DMODELC;
        const float* b2_l  = b2  + (long long)l * DMODELC;

        // x_mem = [memory[l]; core]
        cudaMemcpyAsync(xmem, memory + (long long)l * LSLOT, LSLOT * sizeof(float),
                        cudaMemcpyDeviceToDevice, 0);
        cudaMemcpyAsync(xmem + LSLOT, core, LSLOT * sizeof(float),
                        cudaMemcpyDeviceToDevice, 0);

        // q = core @ Wq
        launch_tg<128, false, 0>(core, Wq_l, q, nullptr,
            DMODELC / 128, NT / 128, 1, DMODELC, DMODELC, DMODELC, DMODELC);
        qwqr_k<<<(NT * DMODELC) / 256, 256>>>(q, rwb, rrb, qw, qr);

        // kv = xmem @ Wkv
        launch_tg<128, false, 0>(xmem, Wkv_l, kv, nullptr,
            2 * DMODELC / 128, KT / 128, 1, DMODELC, DMODELC, 2 * DMODELC, 2 * DMODELC);

        // r_k = pos @ Wr
        launch_tg<128, false, 0>(pos, Wr_l, rk, nullptr,
            DMODELC / 128, KLENC / 128, 1, DMODELC, DMODELC, DMODELC, DMODELC);

        // AC[b,n] = qw[512,64] @ k^T
        launch_tg<128, true, 0>(qw, kv, scores, nullptr,
            KLENC / 128, QLENC / 128, BSZC * NHEADC,
            DHEADC, BSZC * DMODELC, BSZC * 2 * DMODELC, KLENC,
            NHEADC,
            DMODELC, DHEADC,
            2 * DMODELC, DHEADC,
            (long long)NHEADC * QLENC * KLENC, (long long)QLENC * KLENC);

        // BD_raw[n] = qr[4096,64] @ rk^T
        launch_tg<128, true, 0>(qr, rk, bdp, nullptr,
            KLENC / 128, NT / 128, NHEADC,
            DHEADC, DMODELC, DMODELC, KLENC,
            NHEADC,
            0, DHEADC, 0, DHEADC, 0, (long long)NT * KLENC);

        softmax_k<<<dim3(QLENC, BSZC * NHEADC), 256>>>(scores, bdp, probs);

        // vec[b,n] = probs[512,1024] @ v[1024,64]   (BN=64 tile)
        launch_tg<64, false, 0>(probs, kv + DMODELC, vec, nullptr,
            1, QLENC / 128, BSZC * NHEADC,
            KLENC, KLENC, BSZC * 2 * DMODELC, BSZC * DMODELC,
            NHEADC,
            (long long)NHEADC * QLENC * KLENC, (long long)QLENC * KLENC,
            2 * DMODELC, DHEADC,
            DMODELC, DHEADC);

        // attn_out = vec @ Wo
        launch_tg<128, false, 0>(vec, Wo_l, tmp, nullptr,
            DMODELC / 128, NT / 128, 1, DMODELC, DMODELC, DMODELC, DMODELC);

        ln_k<<<NT, 256>>>(core, tmp, ln1g + l * DMODELC, ln1b + l * DMODELC,
                          core, nullptr);

        // h1 = relu(core @ W1 + b1)
        launch_tg<128, false, 2>(core, W1_l, h1, b1_l,
            DINNERC / 128, NT / 128, 1, DMODELC, DMODELC, DINNERC, DINNERC);

        // ff = h1 @ W2 + b2
        launch_tg<128, false, 1>(h1, W2_l, tmp, b2_l,
            DMODELC / 128, NT / 128, 1, DINNERC, DINNERC, DMODELC, DMODELC);

        float* memout = (l < NLAYERC - 1) ? (mems_out + (long long)(l + 1) * LSLOT)
                                          : nullptr;
        ln_k<<<NT, 256>>>(core, tmp, ln2g + l * DMODELC, ln2b + l * DMODELC,
                          core, memout);
    }

    // logits = coreb @ embb^T (bf16 tensor cores, loss-only path)
    conv_k<<<(NT * DMODELC) / 1024, 256>>>(core, coreb, NT * DMODELC);
    bgemm_k<<<dim3(NTOKC / 128, NT / 128, 1), 256>>>(
        coreb, embb, logits, DMODELC, DMODELC, DMODELC, NTOKC);

    loss_k<<<NT, 256>>>(logits, target, out);
}